// round 1
// baseline (speedup 1.0000x reference)
#include <cuda_runtime.h>
#include <mma.h>
#include <math.h>

using namespace nvcuda;

#define BB 2
#define TT 2048
#define DD 1024
#define HH 16
#define HD 64
#define NROWS (BB*TT)      // 4096
#define WINDOW 128

// ---------------- scratch (device globals: allocation-free) ----------------
__device__ float g_q[(size_t)BB*HH*TT*HD];   // [B,H,T,64] normalized q
__device__ float g_k[(size_t)BB*HH*TT*HD];   // [B,H,T,64] normalized k
__device__ float g_v[(size_t)BB*HH*TT*HD];   // [B,H,T,64]
__device__ float g_att[(size_t)NROWS*DD];    // [B,T,D] merged attention output

__device__ __forceinline__ float tf32r(float x){
    unsigned u;
    asm("cvt.rna.tf32.f32 %0, %1;" : "=r"(u) : "f"(x));
    return __uint_as_float(u);
}

// =====================================================================
// GEMM kernel (3xTF32 split precision, fp32 accumulate)
//   mode 0: A = x [4096,1024]; N = 3072 columns over (Wq|Wk|Wv).
//           Epilogue: per-head L2 norm for q/k, scatter to g_q/g_k/g_v.
//   mode 1: A = g_att; N = 1024 (Wo); write to d_out [B,T,D].
// Tiles: BM=64, BN=64, BK=32. 256 threads (8 warps), each warp 16x32 of C.
// smem: Ah/Al/Bh/Bl [64][36] fp32 (tf32-rounded hi/lo); C staged in-place.
// =====================================================================
#define GEMM_SMEM_FLOATS (4*64*36)
#define GEMM_SMEM_BYTES  (GEMM_SMEM_FLOATS*4)

__global__ void __launch_bounds__(256) gemm_kernel(
    const float* __restrict__ Ain,
    const float* __restrict__ W0, const float* __restrict__ W1, const float* __restrict__ W2,
    float* __restrict__ out, int mode)
{
    extern __shared__ float sm[];
    float* Ah = sm;
    float* Al = sm + 64*36;
    float* Bh = sm + 2*64*36;
    float* Bl = sm + 3*64*36;
    float* Cs = sm;                      // reused after mainloop, [64][68]

    const int tid = threadIdx.x, w = tid >> 5, lane = tid & 31;
    const int r0 = blockIdx.y * 64;
    const int nb = blockIdx.x * 64;

    const float* A = (mode == 0) ? Ain : g_att;
    const float* W;
    int which, col0;
    if (mode == 0){ which = nb >> 10; col0 = nb & 1023;
                    W = (which==0) ? W0 : ((which==1) ? W1 : W2); }
    else          { which = 3; col0 = nb; W = W0; }

    wmma::fragment<wmma::accumulator,16,16,8,float> acc[2];
    wmma::fill_fragment(acc[0], 0.0f);
    wmma::fill_fragment(acc[1], 0.0f);
    const int wr = w & 3, wc = w >> 2;

    for (int k0 = 0; k0 < DD; k0 += 32){
        // cooperative load of A[64x32] and B(=W rows)[64x32], split hi/lo
        #pragma unroll
        for (int it = 0; it < 2; it++){
            int idx  = tid + it*256;          // 0..511 -> 64 rows x 8 float4
            int rrow = idx >> 3;
            int c4   = (idx & 7) << 2;
            float4 av = *(const float4*)(A + (size_t)(r0 + rrow)*DD + k0 + c4);
            float4 bv = *(const float4*)(W + (size_t)(col0 + rrow)*DD + k0 + c4);
            int o = rrow*36 + c4;
            float h0=tf32r(av.x), h1=tf32r(av.y), h2=tf32r(av.z), h3=tf32r(av.w);
            Ah[o]=h0; Ah[o+1]=h1; Ah[o+2]=h2; Ah[o+3]=h3;
            Al[o]=tf32r(av.x-h0); Al[o+1]=tf32r(av.y-h1); Al[o+2]=tf32r(av.z-h2); Al[o+3]=tf32r(av.w-h3);
            h0=tf32r(bv.x); h1=tf32r(bv.y); h2=tf32r(bv.z); h3=tf32r(bv.w);
            Bh[o]=h0; Bh[o+1]=h1; Bh[o+2]=h2; Bh[o+3]=h3;
            Bl[o]=tf32r(bv.x-h0); Bl[o+1]=tf32r(bv.y-h1); Bl[o+2]=tf32r(bv.z-h2); Bl[o+3]=tf32r(bv.w-h3);
        }
        __syncthreads();
        #pragma unroll
        for (int kk = 0; kk < 32; kk += 8){
            wmma::fragment<wmma::matrix_a,16,16,8,wmma::precision::tf32,wmma::row_major> ah, al;
            wmma::load_matrix_sync(ah, Ah + wr*16*36 + kk, 36);
            wmma::load_matrix_sync(al, Al + wr*16*36 + kk, 36);
            #pragma unroll
            for (int f = 0; f < 2; f++){
                wmma::fragment<wmma::matrix_b,16,16,8,wmma::precision::tf32,wmma::col_major> bh, bl;
                int n0 = wc*32 + f*16;
                wmma::load_matrix_sync(bh, Bh + n0*36 + kk, 36);
                wmma::load_matrix_sync(bl, Bl + n0*36 + kk, 36);
                wmma::mma_sync(acc[f], ah, bh, acc[f]);   // hi*hi
                wmma::mma_sync(acc[f], ah, bl, acc[f]);   // hi*lo
                wmma::mma_sync(acc[f], al, bh, acc[f]);   // lo*hi
            }
        }
        __syncthreads();
    }

    wmma::store_matrix_sync(Cs + wr*16*68 + wc*32,      acc[0], 68, wmma::mem_row_major);
    wmma::store_matrix_sync(Cs + wr*16*68 + wc*32 + 16, acc[1], 68, wmma::mem_row_major);
    __syncthreads();

    // epilogue: warp w handles rows [w*8, w*8+8); lane covers cols {lane, lane+32}
    #pragma unroll
    for (int rr = 0; rr < 8; rr++){
        int row = w*8 + rr;
        float v0 = Cs[row*68 + lane];
        float v1 = Cs[row*68 + lane + 32];
        int gt = r0 + row;
        if (mode == 0){
            float scale = 1.0f;
            if (which < 2){                       // l2norm for q, k (tile == one head)
                float ss = v0*v0 + v1*v1;
                #pragma unroll
                for (int o = 16; o; o >>= 1) ss += __shfl_xor_sync(0xffffffffu, ss, o);
                scale = 1.0f / fmaxf(sqrtf(ss), 1e-6f);
            }
            int bidx = gt >> 11, t = gt & (TT-1);
            int hh = col0 >> 6;
            float* dst = ((which==0) ? g_q : ((which==1) ? g_k : g_v))
                         + ((size_t)(bidx*HH + hh)*TT + t)*HD;
            dst[lane]      = v0*scale;
            dst[lane + 32] = v1*scale;
        } else {
            out[(size_t)gt*DD + nb + lane]      = v0;
            out[(size_t)gt*DD + nb + lane + 32] = v1;
        }
    }
}

// =====================================================================
// Attention kernel: one block per (b, h, 64-query tile).
// Keys for queries [q0, q0+63] span [q0, q0+190] -> 192-key tile (tail zero/masked).
// S = Q K^T (wmma tf32), ALiBi + window mask + softmax in fp32, O = P V (wmma tf32).
// smem: Qs[64][68], Ks[192][68], Vs[192][68], Ss[64][200]  = 173056 B
// =====================================================================
#define ATTN_SMEM_FLOATS (64*68 + 192*68 + 192*68 + 64*200)
#define ATTN_SMEM_BYTES  (ATTN_SMEM_FLOATS*4)

__global__ void __launch_bounds__(256) attn_kernel()
{
    extern __shared__ float sm[];
    float* Qs = sm;                  // [64][68]
    float* Ks = sm + 64*68;          // [192][68]  (row j, dims contiguous)
    float* Vs = Ks + 192*68;         // [192][68]
    float* Ss = Vs + 192*68;         // [64][200]

    const int tid = threadIdx.x, w = tid >> 5, lane = tid & 31;
    const int q0 = blockIdx.x * 64;
    const int h  = blockIdx.y, b = blockIdx.z;
    const size_t base = ((size_t)(b*HH + h)*TT)*HD;
    const float* qb = g_q + base;
    const float* kb = g_k + base;
    const float* vb = g_v + base;

    #pragma unroll
    for (int it = 0; it < 4; it++){             // Q: 64x64
        int idx = tid + it*256;
        int row = idx >> 4, c4 = (idx & 15) << 2;
        float4 v = *(const float4*)(qb + (size_t)(q0 + row)*HD + c4);
        int o = row*68 + c4;
        Qs[o]=tf32r(v.x); Qs[o+1]=tf32r(v.y); Qs[o+2]=tf32r(v.z); Qs[o+3]=tf32r(v.w);
    }
    #pragma unroll
    for (int it = 0; it < 12; it++){            // K,V: 192x64 (zero-pad past T)
        int idx = tid + it*256;
        int row = idx >> 4, c4 = (idx & 15) << 2;
        int jg = q0 + row;
        float4 kv = make_float4(0.f,0.f,0.f,0.f), vv = kv;
        if (jg < TT){
            kv = *(const float4*)(kb + (size_t)jg*HD + c4);
            vv = *(const float4*)(vb + (size_t)jg*HD + c4);
        }
        int o = row*68 + c4;
        Ks[o]=tf32r(kv.x); Ks[o+1]=tf32r(kv.y); Ks[o+2]=tf32r(kv.z); Ks[o+3]=tf32r(kv.w);
        Vs[o]=tf32r(vv.x); Vs[o+1]=tf32r(vv.y); Vs[o+2]=tf32r(vv.z); Vs[o+3]=tf32r(vv.w);
    }
    __syncthreads();

    const int wr = w & 3, wc = w >> 2;          // 4 row-bands x 2 col-bands

    {   // S[64,192] = Q @ K^T
        wmma::fragment<wmma::accumulator,16,16,8,float> acc[6];
        #pragma unroll
        for (int f = 0; f < 6; f++) wmma::fill_fragment(acc[f], 0.0f);
        #pragma unroll
        for (int d = 0; d < HD; d += 8){
            wmma::fragment<wmma::matrix_a,16,16,8,wmma::precision::tf32,wmma::row_major> af;
            wmma::load_matrix_sync(af, Qs + wr*16*68 + d, 68);
            #pragma unroll
            for (int f = 0; f < 6; f++){
                wmma::fragment<wmma::matrix_b,16,16,8,wmma::precision::tf32,wmma::col_major> bf;
                wmma::load_matrix_sync(bf, Ks + (wc*96 + f*16)*68 + d, 68);
                wmma::mma_sync(acc[f], af, bf, acc[f]);
            }
        }
        #pragma unroll
        for (int f = 0; f < 6; f++)
            wmma::store_matrix_sync(Ss + wr*16*200 + wc*96 + f*16, acc[f], 200,
                                    wmma::mem_row_major);
    }
    __syncthreads();

    // softmax with ALiBi + sliding-window mask: allowed cols [row, row+127] & in-range
    const float slope = exp2f(-8.0f * (float)h / 15.0f);
    #pragma unroll
    for (int rr = 0; rr < 8; rr++){
        int row = w*8 + rr;
        float vals[6];
        float m = -INFINITY;
        #pragma unroll
        for (int i = 0; i < 6; i++){
            int col = lane + 32*i;
            bool ok = (col >= row) && (col < row + WINDOW) && (q0 + col < TT);
            float s = ok ? (Ss[row*200 + col] - (float)(col - row)*slope) : -INFINITY;
            vals[i] = s;
            m = fmaxf(m, s);
        }
        #pragma unroll
        for (int o = 16; o; o >>= 1) m = fmaxf(m, __shfl_xor_sync(0xffffffffu, m, o));
        float sum = 0.0f;
        #pragma unroll
        for (int i = 0; i < 6; i++){
            float p = (vals[i] > -INFINITY) ? __expf(vals[i] - m) : 0.0f;
            vals[i] = p; sum += p;
        }
        #pragma unroll
        for (int o = 16; o; o >>= 1) sum += __shfl_xor_sync(0xffffffffu, sum, o);
        float inv = 1.0f / sum;
        #pragma unroll
        for (int i = 0; i < 6; i++){
            int col = lane + 32*i;
            Ss[row*200 + col] = tf32r(vals[i]*inv);
        }
    }
    __syncthreads();

    {   // O[64,64] = P @ V
        wmma::fragment<wmma::accumulator,16,16,8,float> acc[2];
        wmma::fill_fragment(acc[0], 0.0f);
        wmma::fill_fragment(acc[1], 0.0f);
        #pragma unroll
        for (int j = 0; j < 192; j += 8){
            wmma::fragment<wmma::matrix_a,16,16,8,wmma::precision::tf32,wmma::row_major> af;
            wmma::load_matrix_sync(af, Ss + wr*16*200 + j, 200);
            #pragma unroll
            for (int f = 0; f < 2; f++){
                wmma::fragment<wmma::matrix_b,16,16,8,wmma::precision::tf32,wmma::row_major> bf;
                wmma::load_matrix_sync(bf, Vs + j*68 + wc*32 + f*16, 68);
                wmma::mma_sync(acc[f], af, bf, acc[f]);
            }
        }
        wmma::store_matrix_sync(Qs + wr*16*68 + wc*32,      acc[0], 68, wmma::mem_row_major);
        wmma::store_matrix_sync(Qs + wr*16*68 + wc*32 + 16, acc[1], 68, wmma::mem_row_major);
    }
    __syncthreads();

    #pragma unroll
    for (int it = 0; it < 4; it++){             // write merged [B,T,D]
        int idx = tid + it*256;
        int row = idx >> 4, c4 = (idx & 15) << 2;
        float4 v = *(const float4*)(Qs + row*68 + c4);
        *(float4*)(g_att + (size_t)(b*TT + q0 + row)*DD + h*HD + c4) = v;
    }
}

// =====================================================================
extern "C" void kernel_launch(void* const* d_in, const int* in_sizes, int n_in,
                              void* d_out, int out_size)
{
    const float* x  = (const float*)d_in[0];
    const float* Wq = (const float*)d_in[1];
    const float* Wk = (const float*)d_in[2];
    const float* Wv = (const float*)d_in[3];
    const float* Wo = (const float*)d_in[4];
    float* out = (float*)d_out;

    cudaFuncSetAttribute(attn_kernel, cudaFuncAttributeMaxDynamicSharedMemorySize,
                         ATTN_SMEM_BYTES);

    // 1) fused QKV projection + per-head l2norm (q,k)
    gemm_kernel<<<dim3(48, 64), 256, GEMM_SMEM_BYTES>>>(x, Wq, Wk, Wv, nullptr, 0);
    // 2) sliding-window attention per (b, h, 64-query tile)
    attn_kernel<<<dim3(TT/64, HH, BB), 256, ATTN_SMEM_BYTES>>>();
    // 3) output projection
    gemm_kernel<<<dim3(16, 64), 256, GEMM_SMEM_BYTES>>>(nullptr, Wo, nullptr, nullptr, out, 1);
}

// round 2
// speedup vs baseline: 2.5181x; 2.5181x over previous
#include <cuda_runtime.h>
#include <cuda_bf16.h>
#include <mma.h>
#include <math.h>

using namespace nvcuda;

#define BB 2
#define TT 2048
#define DD 1024
#define HH 16
#define HD 64
#define NROWS (BB*TT)      // 4096
#define WINDOW 128

// ---------------- scratch (device globals: allocation-free) ----------------
__device__ float g_q[(size_t)BB*HH*TT*HD];   // [B,H,T,64] normalized q
__device__ float g_k[(size_t)BB*HH*TT*HD];   // [B,H,T,64] normalized k
__device__ float g_v[(size_t)BB*HH*TT*HD];   // [B,H,T,64]
__device__ float g_att[(size_t)NROWS*DD];    // [B,T,D] merged attention output

__device__ __forceinline__ float tf32r(float x){
    unsigned u;
    asm("cvt.rna.tf32.f32 %0, %1;" : "=r"(u) : "f"(x));
    return __uint_as_float(u);
}

// =====================================================================
// GEMM kernel (3xBF16 split precision, fp32 accumulate)
//   mode 0: A = x [4096,1024]; N = 3072 columns over (Wq|Wk|Wv).
//           Epilogue: per-head L2 norm for q/k, scatter to g_q/g_k/g_v.
//   mode 1: A = g_att; N = 1024 (Wo); write to d_out [B,T,D].
// Tiles: BM=128, BN=64, BK=64. 256 threads (8 warps), warp = 32x32 of C.
// smem (bf16, stride 72): Ah/Al [128][72], Bh/Bl [64][72]  = 55296 B
// =====================================================================
#define GK_STRIDE 72
#define GEMM_SMEM_BYTES (2*(128*GK_STRIDE*2) + 2*(64*GK_STRIDE*2))  // 55296

__global__ void __launch_bounds__(256) gemm_kernel(
    const float* __restrict__ Ain,
    const float* __restrict__ W0, const float* __restrict__ W1, const float* __restrict__ W2,
    float* __restrict__ out, int mode)
{
    extern __shared__ char smraw[];
    __nv_bfloat16* Ah = (__nv_bfloat16*)smraw;                 // [128][72]
    __nv_bfloat16* Al = Ah + 128*GK_STRIDE;
    __nv_bfloat16* Bh = Al + 128*GK_STRIDE;                    // [64][72]
    __nv_bfloat16* Bl = Bh + 64*GK_STRIDE;
    float* Cs = (float*)smraw;                                 // reused, [128][68]

    const int tid = threadIdx.x, w = tid >> 5, lane = tid & 31;
    const int r0 = blockIdx.y * 128;
    const int nb = blockIdx.x * 64;

    const float* A = (mode == 0) ? Ain : g_att;
    const float* W;
    int which, col0;
    if (mode == 0){ which = nb >> 10; col0 = nb & 1023;
                    W = (which==0) ? W0 : ((which==1) ? W1 : W2); }
    else          { which = 3; col0 = nb; W = W0; }

    wmma::fragment<wmma::accumulator,16,16,16,float> acc[2][2];
    #pragma unroll
    for (int i = 0; i < 2; i++)
        #pragma unroll
        for (int j = 0; j < 2; j++) wmma::fill_fragment(acc[i][j], 0.0f);

    const int wr = w >> 1, wc = w & 1;   // warp -> rows [wr*32,+32), cols [wc*32,+32)

    for (int k0 = 0; k0 < DD; k0 += 64){
        // ---- load A[128x64] -> hi/lo bf16 ----
        #pragma unroll
        for (int it = 0; it < 8; it++){
            int idx = tid + it*256;              // 2048 float4
            int row = idx >> 4, c4 = (idx & 15) << 2;
            float4 av = *(const float4*)(A + (size_t)(r0 + row)*DD + k0 + c4);
            __nv_bfloat16 h0=__float2bfloat16(av.x), h1=__float2bfloat16(av.y),
                          h2=__float2bfloat16(av.z), h3=__float2bfloat16(av.w);
            __nv_bfloat162* dh = (__nv_bfloat162*)(Ah + row*GK_STRIDE + c4);
            dh[0] = __nv_bfloat162(h0, h1); dh[1] = __nv_bfloat162(h2, h3);
            __nv_bfloat162* dl = (__nv_bfloat162*)(Al + row*GK_STRIDE + c4);
            dl[0] = __nv_bfloat162(__float2bfloat16(av.x - __bfloat162float(h0)),
                                   __float2bfloat16(av.y - __bfloat162float(h1)));
            dl[1] = __nv_bfloat162(__float2bfloat16(av.z - __bfloat162float(h2)),
                                   __float2bfloat16(av.w - __bfloat162float(h3)));
        }
        // ---- load B[64x64] (= W rows col0..col0+63) -> hi/lo bf16 ----
        #pragma unroll
        for (int it = 0; it < 4; it++){
            int idx = tid + it*256;              // 1024 float4
            int row = idx >> 4, c4 = (idx & 15) << 2;
            float4 bv = *(const float4*)(W + (size_t)(col0 + row)*DD + k0 + c4);
            __nv_bfloat16 h0=__float2bfloat16(bv.x), h1=__float2bfloat16(bv.y),
                          h2=__float2bfloat16(bv.z), h3=__float2bfloat16(bv.w);
            __nv_bfloat162* dh = (__nv_bfloat162*)(Bh + row*GK_STRIDE + c4);
            dh[0] = __nv_bfloat162(h0, h1); dh[1] = __nv_bfloat162(h2, h3);
            __nv_bfloat162* dl = (__nv_bfloat162*)(Bl + row*GK_STRIDE + c4);
            dl[0] = __nv_bfloat162(__float2bfloat16(bv.x - __bfloat162float(h0)),
                                   __float2bfloat16(bv.y - __bfloat162float(h1)));
            dl[1] = __nv_bfloat162(__float2bfloat16(bv.z - __bfloat162float(h2)),
                                   __float2bfloat16(bv.w - __bfloat162float(h3)));
        }
        __syncthreads();

        #pragma unroll
        for (int kk = 0; kk < 64; kk += 16){
            wmma::fragment<wmma::matrix_a,16,16,16,__nv_bfloat16,wmma::row_major> ah[2], al[2];
            wmma::fragment<wmma::matrix_b,16,16,16,__nv_bfloat16,wmma::col_major> bh[2], bl[2];
            #pragma unroll
            for (int i = 0; i < 2; i++){
                wmma::load_matrix_sync(ah[i], Ah + (wr*32 + i*16)*GK_STRIDE + kk, GK_STRIDE);
                wmma::load_matrix_sync(al[i], Al + (wr*32 + i*16)*GK_STRIDE + kk, GK_STRIDE);
                wmma::load_matrix_sync(bh[i], Bh + (wc*32 + i*16)*GK_STRIDE + kk, GK_STRIDE);
                wmma::load_matrix_sync(bl[i], Bl + (wc*32 + i*16)*GK_STRIDE + kk, GK_STRIDE);
            }
            #pragma unroll
            for (int i = 0; i < 2; i++)
                #pragma unroll
                for (int j = 0; j < 2; j++){
                    wmma::mma_sync(acc[i][j], ah[i], bh[j], acc[i][j]);  // hi*hi
                    wmma::mma_sync(acc[i][j], ah[i], bl[j], acc[i][j]);  // hi*lo
                    wmma::mma_sync(acc[i][j], al[i], bh[j], acc[i][j]);  // lo*hi
                }
        }
        __syncthreads();
    }

    // ---- stage C into smem ----
    #pragma unroll
    for (int i = 0; i < 2; i++)
        #pragma unroll
        for (int j = 0; j < 2; j++)
            wmma::store_matrix_sync(Cs + (wr*32 + i*16)*68 + wc*32 + j*16,
                                    acc[i][j], 68, wmma::mem_row_major);
    __syncthreads();

    // ---- epilogue: warp w -> rows [w*16, w*16+16), lane -> cols {lane, lane+32}
    #pragma unroll
    for (int rr = 0; rr < 16; rr++){
        int row = w*16 + rr;
        float v0 = Cs[row*68 + lane];
        float v1 = Cs[row*68 + lane + 32];
        int gt = r0 + row;
        if (mode == 0){
            float scale = 1.0f;
            if (which < 2){                       // l2norm for q, k (tile == one head)
                float ss = v0*v0 + v1*v1;
                #pragma unroll
                for (int o = 16; o; o >>= 1) ss += __shfl_xor_sync(0xffffffffu, ss, o);
                scale = 1.0f / fmaxf(sqrtf(ss), 1e-6f);
            }
            int bidx = gt >> 11, t = gt & (TT-1);
            int hh = col0 >> 6;
            float* dst = ((which==0) ? g_q : ((which==1) ? g_k : g_v))
                         + ((size_t)(bidx*HH + hh)*TT + t)*HD;
            dst[lane]      = v0*scale;
            dst[lane + 32] = v1*scale;
        } else {
            out[(size_t)gt*DD + nb + lane]      = v0;
            out[(size_t)gt*DD + nb + lane + 32] = v1;
        }
    }
}

// =====================================================================
// Attention kernel: one block per (b, h, 64-query tile).  (unchanged, tf32)
// Keys for queries [q0, q0+63] span [q0, q0+190] -> 192-key tile.
// smem: Qs[64][68], Ks[192][68], Vs[192][68], Ss[64][200]  = 173056 B
// =====================================================================
#define ATTN_SMEM_FLOATS (64*68 + 192*68 + 192*68 + 64*200)
#define ATTN_SMEM_BYTES  (ATTN_SMEM_FLOATS*4)

__global__ void __launch_bounds__(256) attn_kernel()
{
    extern __shared__ float sm[];
    float* Qs = sm;                  // [64][68]
    float* Ks = sm + 64*68;          // [192][68]
    float* Vs = Ks + 192*68;         // [192][68]
    float* Ss = Vs + 192*68;         // [64][200]

    const int tid = threadIdx.x, w = tid >> 5, lane = tid & 31;
    const int q0 = blockIdx.x * 64;
    const int h  = blockIdx.y, b = blockIdx.z;
    const size_t base = ((size_t)(b*HH + h)*TT)*HD;
    const float* qb = g_q + base;
    const float* kb = g_k + base;
    const float* vb = g_v + base;

    #pragma unroll
    for (int it = 0; it < 4; it++){             // Q: 64x64
        int idx = tid + it*256;
        int row = idx >> 4, c4 = (idx & 15) << 2;
        float4 v = *(const float4*)(qb + (size_t)(q0 + row)*HD + c4);
        int o = row*68 + c4;
        Qs[o]=tf32r(v.x); Qs[o+1]=tf32r(v.y); Qs[o+2]=tf32r(v.z); Qs[o+3]=tf32r(v.w);
    }
    #pragma unroll
    for (int it = 0; it < 12; it++){            // K,V: 192x64 (zero-pad past T)
        int idx = tid + it*256;
        int row = idx >> 4, c4 = (idx & 15) << 2;
        int jg = q0 + row;
        float4 kv = make_float4(0.f,0.f,0.f,0.f), vv = kv;
        if (jg < TT){
            kv = *(const float4*)(kb + (size_t)jg*HD + c4);
            vv = *(const float4*)(vb + (size_t)jg*HD + c4);
        }
        int o = row*68 + c4;
        Ks[o]=tf32r(kv.x); Ks[o+1]=tf32r(kv.y); Ks[o+2]=tf32r(kv.z); Ks[o+3]=tf32r(kv.w);
        Vs[o]=tf32r(vv.x); Vs[o+1]=tf32r(vv.y); Vs[o+2]=tf32r(vv.z); Vs[o+3]=tf32r(vv.w);
    }
    __syncthreads();

    const int wr = w & 3, wc = w >> 2;          // 4 row-bands x 2 col-bands

    {   // S[64,192] = Q @ K^T
        wmma::fragment<wmma::accumulator,16,16,8,float> acc[6];
        #pragma unroll
        for (int f = 0; f < 6; f++) wmma::fill_fragment(acc[f], 0.0f);
        #pragma unroll
        for (int d = 0; d < HD; d += 8){
            wmma::fragment<wmma::matrix_a,16,16,8,wmma::precision::tf32,wmma::row_major> af;
            wmma::load_matrix_sync(af, Qs + wr*16*68 + d, 68);
            #pragma unroll
            for (int f = 0; f < 6; f++){
                wmma::fragment<wmma::matrix_b,16,16,8,wmma::precision::tf32,wmma::col_major> bf;
                wmma::load_matrix_sync(bf, Ks + (wc*96 + f*16)*68 + d, 68);
                wmma::mma_sync(acc[f], af, bf, acc[f]);
            }
        }
        #pragma unroll
        for (int f = 0; f < 6; f++)
            wmma::store_matrix_sync(Ss + wr*16*200 + wc*96 + f*16, acc[f], 200,
                                    wmma::mem_row_major);
    }
    __syncthreads();

    // softmax with ALiBi + sliding-window mask: allowed cols [row, row+127] & in-range
    const float slope = exp2f(-8.0f * (float)h / 15.0f);
    #pragma unroll
    for (int rr = 0; rr < 8; rr++){
        int row = w*8 + rr;
        float vals[6];
        float m = -INFINITY;
        #pragma unroll
        for (int i = 0; i < 6; i++){
            int col = lane + 32*i;
            bool ok = (col >= row) && (col < row + WINDOW) && (q0 + col < TT);
            float s = ok ? (Ss[row*200 + col] - (float)(col - row)*slope) : -INFINITY;
            vals[i] = s;
            m = fmaxf(m, s);
        }
        #pragma unroll
        for (int o = 16; o; o >>= 1) m = fmaxf(m, __shfl_xor_sync(0xffffffffu, m, o));
        float sum = 0.0f;
        #pragma unroll
        for (int i = 0; i < 6; i++){
            float p = (vals[i] > -INFINITY) ? __expf(vals[i] - m) : 0.0f;
            vals[i] = p; sum += p;
        }
        #pragma unroll
        for (int o = 16; o; o >>= 1) sum += __shfl_xor_sync(0xffffffffu, sum, o);
        float inv = 1.0f / sum;
        #pragma unroll
        for (int i = 0; i < 6; i++){
            int col = lane + 32*i;
            Ss[row*200 + col] = tf32r(vals[i]*inv);
        }
    }
    __syncthreads();

    {   // O[64,64] = P @ V
        wmma::fragment<wmma::accumulator,16,16,8,float> acc[2];
        wmma::fill_fragment(acc[0], 0.0f);
        wmma::fill_fragment(acc[1], 0.0f);
        #pragma unroll
        for (int j = 0; j < 192; j += 8){
            wmma::fragment<wmma::matrix_a,16,16,8,wmma::precision::tf32,wmma::row_major> af;
            wmma::load_matrix_sync(af, Ss + wr*16*200 + j, 200);
            #pragma unroll
            for (int f = 0; f < 2; f++){
                wmma::fragment<wmma::matrix_b,16,16,8,wmma::precision::tf32,wmma::row_major> bf;
                wmma::load_matrix_sync(bf, Vs + j*68 + wc*32 + f*16, 68);
                wmma::mma_sync(acc[f], af, bf, acc[f]);
            }
        }
        wmma::store_matrix_sync(Qs + wr*16*68 + wc*32,      acc[0], 68, wmma::mem_row_major);
        wmma::store_matrix_sync(Qs + wr*16*68 + wc*32 + 16, acc[1], 68, wmma::mem_row_major);
    }
    __syncthreads();

    #pragma unroll
    for (int it = 0; it < 4; it++){             // write merged [B,T,D]
        int idx = tid + it*256;
        int row = idx >> 4, c4 = (idx & 15) << 2;
        float4 v = *(const float4*)(Qs + row*68 + c4);
        *(float4*)(g_att + (size_t)(b*TT + q0 + row)*DD + h*HD + c4) = v;
    }
}

// =====================================================================
extern "C" void kernel_launch(void* const* d_in, const int* in_sizes, int n_in,
                              void* d_out, int out_size)
{
    const float* x  = (const float*)d_in[0];
    const float* Wq = (const float*)d_in[1];
    const float* Wk = (const float*)d_in[2];
    const float* Wv = (const float*)d_in[3];
    const float* Wo = (const float*)d_in[4];
    float* out = (float*)d_out;

    cudaFuncSetAttribute(gemm_kernel, cudaFuncAttributeMaxDynamicSharedMemorySize,
                         GEMM_SMEM_BYTES);
    cudaFuncSetAttribute(attn_kernel, cudaFuncAttributeMaxDynamicSharedMemorySize,
                         ATTN_SMEM_BYTES);

    // 1) fused QKV projection + per-head l2norm (q,k)  [M=4096 x N=3072]
    gemm_kernel<<<dim3(48, 32), 256, GEMM_SMEM_BYTES>>>(x, Wq, Wk, Wv, nullptr, 0);
    // 2) sliding-window attention per (b, h, 64-query tile)
    attn_kernel<<<dim3(TT/64, HH, BB), 256, ATTN_SMEM_BYTES>>>();
    // 3) output projection  [M=4096 x N=1024]
    gemm_kernel<<<dim3(16, 32), 256, GEMM_SMEM_BYTES>>>(nullptr, Wo, nullptr, nullptr, out, 1);
}

// round 3
// speedup vs baseline: 2.9296x; 1.1634x over previous
#include <cuda_runtime.h>
#include <cuda_bf16.h>
#include <mma.h>
#include <math.h>

using namespace nvcuda;

#define BB 2
#define TT 2048
#define DD 1024
#define HH 16
#define HD 64
#define NROWS (BB*TT)      // 4096
#define WINDOW 128
#define MM (1024*1024)

// ---------------- scratch (device globals: allocation-free) ----------------
__device__ float g_q[(size_t)BB*HH*TT*HD];   // [B,H,T,64] normalized q
__device__ float g_k[(size_t)BB*HH*TT*HD];
__device__ float g_v[(size_t)BB*HH*TT*HD];
__device__ __nv_bfloat16 g_xh[(size_t)NROWS*DD];   // x split hi/lo
__device__ __nv_bfloat16 g_xl[(size_t)NROWS*DD];
__device__ __nv_bfloat16 g_wh[(size_t)4*MM];       // Wq|Wk|Wv|Wo split hi
__device__ __nv_bfloat16 g_wl[(size_t)4*MM];
__device__ __nv_bfloat16 g_ath[(size_t)NROWS*DD];  // attention out split hi/lo
__device__ __nv_bfloat16 g_atl[(size_t)NROWS*DD];

__device__ __forceinline__ float tf32r(float x){
    unsigned u;
    asm("cvt.rna.tf32.f32 %0, %1;" : "=r"(u) : "f"(x));
    return __uint_as_float(u);
}

__device__ __forceinline__ void cp_async16(void* smem, const void* gmem){
    unsigned s = (unsigned)__cvta_generic_to_shared(smem);
    asm volatile("cp.async.cg.shared.global [%0], [%1], 16;\n" :: "r"(s), "l"(gmem));
}
__device__ __forceinline__ void cp_commit(){ asm volatile("cp.async.commit_group;\n"); }
template<int N> __device__ __forceinline__ void cp_wait(){
    asm volatile("cp.async.wait_group %0;\n" :: "n"(N));
}

// =====================================================================
// split prep: fp32 -> bf16 hi/lo for x and all four weight matrices.
// one float4 per thread; 2,097,152 float4 total.
// =====================================================================
__global__ void __launch_bounds__(256) split_kernel(
    const float* __restrict__ x,
    const float* __restrict__ wq, const float* __restrict__ wk,
    const float* __restrict__ wv, const float* __restrict__ wo)
{
    size_t fi = (size_t)blockIdx.x*256 + threadIdx.x;
    const float* src; __nv_bfloat16 *dh, *dl; size_t base;
    if (fi < 1048576){ src = x; dh = g_xh; dl = g_xl; base = fi; }
    else {
        size_t r = fi - 1048576;
        int m = (int)(r >> 18);
        base = r & 262143;
        src = (m==0)?wq:(m==1)?wk:(m==2)?wv:wo;
        dh = g_wh + (size_t)m*MM; dl = g_wl + (size_t)m*MM;
    }
    float4 v = ((const float4*)src)[base];
    size_t e = base*4;
    __nv_bfloat16 h0=__float2bfloat16(v.x), h1=__float2bfloat16(v.y),
                  h2=__float2bfloat16(v.z), h3=__float2bfloat16(v.w);
    *(__nv_bfloat162*)(dh+e)   = __nv_bfloat162(h0,h1);
    *(__nv_bfloat162*)(dh+e+2) = __nv_bfloat162(h2,h3);
    *(__nv_bfloat162*)(dl+e)   = __nv_bfloat162(__float2bfloat16(v.x-__bfloat162float(h0)),
                                                __float2bfloat16(v.y-__bfloat162float(h1)));
    *(__nv_bfloat162*)(dl+e+2) = __nv_bfloat162(__float2bfloat16(v.z-__bfloat162float(h2)),
                                                __float2bfloat16(v.w-__bfloat162float(h3)));
}

// =====================================================================
// GEMM (3xBF16 split, fp32 acc), cp.async 2-stage pipeline.
// BM=128, BN=128, BK=32. 512 threads / 16 warps, warp = 32x32 of C.
//   mode 0: A = x(split), B = Wq|Wk|Wv by column block; l2norm epilogue.
//   mode 1: A = att(split), B = Wo; write fp32 out.
// smem: 2 stages x {Ah,Al,Bh,Bl}[128][40] bf16 = 81920 B; Cs reuses.
// =====================================================================
#define SROW 40
#define SARR (128*SROW)        // 5120 elems
#define STAGE (4*SARR)         // 20480 elems per stage
#define GEMM_SMEM_BYTES (2*STAGE*2)   // 81920

__global__ void __launch_bounds__(512) gemm_kernel(float* __restrict__ out, int mode)
{
    extern __shared__ __nv_bfloat16 sb[];
    float* Cs = (float*)sb;                       // [128][132] after mainloop

    const int tid = threadIdx.x, w = tid >> 5, lane = tid & 31;
    const int r0 = blockIdx.y * 128;
    const int nb = blockIdx.x * 128;

    int which, col0;
    const __nv_bfloat16 *A_h, *A_l;
    if (mode == 0){ which = nb >> 10; col0 = nb & 1023; A_h = g_xh; A_l = g_xl; }
    else          { which = 3;        col0 = nb;        A_h = g_ath; A_l = g_atl; }
    const __nv_bfloat16* W_h = g_wh + (size_t)which*MM;
    const __nv_bfloat16* W_l = g_wl + (size_t)which*MM;

    // per-thread cp.async coords: 512 threads cover 128 rows x 4 segs of 8 bf16
    const int lrow = tid >> 2;
    const int lseg = (tid & 3) * 8;
    const size_t ga = (size_t)(r0  + lrow)*DD + lseg;
    const size_t gb = (size_t)(col0 + lrow)*DD + lseg;
    const int so = lrow*SROW + lseg;

    wmma::fragment<wmma::accumulator,16,16,16,float> acc[2][2];
    #pragma unroll
    for (int i = 0; i < 2; i++)
        #pragma unroll
        for (int j = 0; j < 2; j++) wmma::fill_fragment(acc[i][j], 0.0f);

    const int wr = w >> 2, wc = w & 3;

    // prefetch chunk 0
    {
        __nv_bfloat16* s = sb;
        cp_async16(s + 0*SARR + so, A_h + ga);
        cp_async16(s + 1*SARR + so, A_l + ga);
        cp_async16(s + 2*SARR + so, W_h + gb);
        cp_async16(s + 3*SARR + so, W_l + gb);
        cp_commit();
    }

    for (int c = 0; c < 32; c++){
        if (c < 31){
            __nv_bfloat16* s = sb + ((c+1)&1)*STAGE;
            size_t ko = (size_t)(c+1)*32;
            cp_async16(s + 0*SARR + so, A_h + ga + ko);
            cp_async16(s + 1*SARR + so, A_l + ga + ko);
            cp_async16(s + 2*SARR + so, W_h + gb + ko);
            cp_async16(s + 3*SARR + so, W_l + gb + ko);
            cp_commit();
            cp_wait<1>();
        } else {
            cp_wait<0>();
        }
        __syncthreads();

        const __nv_bfloat16* s = sb + (c&1)*STAGE;
        const __nv_bfloat16* sAh = s;
        const __nv_bfloat16* sAl = s + SARR;
        const __nv_bfloat16* sBh = s + 2*SARR;
        const __nv_bfloat16* sBl = s + 3*SARR;

        #pragma unroll
        for (int kk = 0; kk < 32; kk += 16){
            wmma::fragment<wmma::matrix_a,16,16,16,__nv_bfloat16,wmma::row_major> ah[2], al[2];
            wmma::fragment<wmma::matrix_b,16,16,16,__nv_bfloat16,wmma::col_major> bh[2], bl[2];
            #pragma unroll
            for (int i = 0; i < 2; i++){
                wmma::load_matrix_sync(ah[i], sAh + (wr*32 + i*16)*SROW + kk, SROW);
                wmma::load_matrix_sync(al[i], sAl + (wr*32 + i*16)*SROW + kk, SROW);
                wmma::load_matrix_sync(bh[i], sBh + (wc*32 + i*16)*SROW + kk, SROW);
                wmma::load_matrix_sync(bl[i], sBl + (wc*32 + i*16)*SROW + kk, SROW);
            }
            #pragma unroll
            for (int i = 0; i < 2; i++)
                #pragma unroll
                for (int j = 0; j < 2; j++){
                    wmma::mma_sync(acc[i][j], ah[i], bh[j], acc[i][j]);
                    wmma::mma_sync(acc[i][j], ah[i], bl[j], acc[i][j]);
                    wmma::mma_sync(acc[i][j], al[i], bh[j], acc[i][j]);
                }
        }
        __syncthreads();
    }

    // stage C in smem
    #pragma unroll
    for (int i = 0; i < 2; i++)
        #pragma unroll
        for (int j = 0; j < 2; j++)
            wmma::store_matrix_sync(Cs + (wr*32 + i*16)*132 + wc*32 + j*16,
                                    acc[i][j], 132, wmma::mem_row_major);
    __syncthreads();

    // epilogue: warp w -> rows [w*8, w*8+8); lane covers 4 cols
    #pragma unroll
    for (int rr = 0; rr < 8; rr++){
        int row = w*8 + rr;
        int gt = r0 + row;
        float v0 = Cs[row*132 + lane];
        float v1 = Cs[row*132 + lane + 32];
        float v2 = Cs[row*132 + lane + 64];
        float v3 = Cs[row*132 + lane + 96];
        if (mode == 0){
            float s0 = 1.0f, s1 = 1.0f;
            if (which < 2){
                float ssa = v0*v0 + v1*v1;
                float ssb = v2*v2 + v3*v3;
                #pragma unroll
                for (int o = 16; o; o >>= 1){
                    ssa += __shfl_xor_sync(0xffffffffu, ssa, o);
                    ssb += __shfl_xor_sync(0xffffffffu, ssb, o);
                }
                s0 = 1.0f / fmaxf(sqrtf(ssa), 1e-6f);
                s1 = 1.0f / fmaxf(sqrtf(ssb), 1e-6f);
            }
            int bidx = gt >> 11, t = gt & (TT-1);
            float* arr = (which==0) ? g_q : ((which==1) ? g_k : g_v);
            int hh0 = col0 >> 6;
            float* d0 = arr + ((size_t)(bidx*HH + hh0  )*TT + t)*HD;
            float* d1 = arr + ((size_t)(bidx*HH + hh0+1)*TT + t)*HD;
            d0[lane]      = v0*s0;
            d0[lane + 32] = v1*s0;
            d1[lane]      = v2*s1;
            d1[lane + 32] = v3*s1;
        } else {
            float* d = out + (size_t)gt*DD + nb;
            d[lane]      = v0;
            d[lane + 32] = v1;
            d[lane + 64] = v2;
            d[lane + 96] = v3;
        }
    }
}

// =====================================================================
// Attention kernel: one block per (b, h, 64-query tile).  (tf32 math)
// Output written as bf16 hi/lo split directly (feeds Wo GEMM).
// smem: Qs[64][68], Ks[192][68], Vs[192][68], Ss[64][200]  = 173056 B
// =====================================================================
#define ATTN_SMEM_FLOATS (64*68 + 192*68 + 192*68 + 64*200)
#define ATTN_SMEM_BYTES  (ATTN_SMEM_FLOATS*4)

__global__ void __launch_bounds__(256) attn_kernel()
{
    extern __shared__ float sm[];
    float* Qs = sm;                  // [64][68]
    float* Ks = sm + 64*68;          // [192][68]
    float* Vs = Ks + 192*68;         // [192][68]
    float* Ss = Vs + 192*68;         // [64][200]

    const int tid = threadIdx.x, w = tid >> 5, lane = tid & 31;
    const int q0 = blockIdx.x * 64;
    const int h  = blockIdx.y, b = blockIdx.z;
    const size_t base = ((size_t)(b*HH + h)*TT)*HD;
    const float* qb = g_q + base;
    const float* kb = g_k + base;
    const float* vb = g_v + base;

    #pragma unroll
    for (int it = 0; it < 4; it++){             // Q: 64x64
        int idx = tid + it*256;
        int row = idx >> 4, c4 = (idx & 15) << 2;
        float4 v = *(const float4*)(qb + (size_t)(q0 + row)*HD + c4);
        int o = row*68 + c4;
        Qs[o]=tf32r(v.x); Qs[o+1]=tf32r(v.y); Qs[o+2]=tf32r(v.z); Qs[o+3]=tf32r(v.w);
    }
    #pragma unroll
    for (int it = 0; it < 12; it++){            // K,V: 192x64 (zero-pad past T)
        int idx = tid + it*256;
        int row = idx >> 4, c4 = (idx & 15) << 2;
        int jg = q0 + row;
        float4 kv = make_float4(0.f,0.f,0.f,0.f), vv = kv;
        if (jg < TT){
            kv = *(const float4*)(kb + (size_t)jg*HD + c4);
            vv = *(const float4*)(vb + (size_t)jg*HD + c4);
        }
        int o = row*68 + c4;
        Ks[o]=tf32r(kv.x); Ks[o+1]=tf32r(kv.y); Ks[o+2]=tf32r(kv.z); Ks[o+3]=tf32r(kv.w);
        Vs[o]=tf32r(vv.x); Vs[o+1]=tf32r(vv.y); Vs[o+2]=tf32r(vv.z); Vs[o+3]=tf32r(vv.w);
    }
    __syncthreads();

    const int wr = w & 3, wc = w >> 2;

    {   // S[64,192] = Q @ K^T
        wmma::fragment<wmma::accumulator,16,16,8,float> acc[6];
        #pragma unroll
        for (int f = 0; f < 6; f++) wmma::fill_fragment(acc[f], 0.0f);
        #pragma unroll
        for (int d = 0; d < HD; d += 8){
            wmma::fragment<wmma::matrix_a,16,16,8,wmma::precision::tf32,wmma::row_major> af;
            wmma::load_matrix_sync(af, Qs + wr*16*68 + d, 68);
            #pragma unroll
            for (int f = 0; f < 6; f++){
                wmma::fragment<wmma::matrix_b,16,16,8,wmma::precision::tf32,wmma::col_major> bf;
                wmma::load_matrix_sync(bf, Ks + (wc*96 + f*16)*68 + d, 68);
                wmma::mma_sync(acc[f], af, bf, acc[f]);
            }
        }
        #pragma unroll
        for (int f = 0; f < 6; f++)
            wmma::store_matrix_sync(Ss + wr*16*200 + wc*96 + f*16, acc[f], 200,
                                    wmma::mem_row_major);
    }
    __syncthreads();

    const float slope = exp2f(-8.0f * (float)h / 15.0f);
    #pragma unroll
    for (int rr = 0; rr < 8; rr++){
        int row = w*8 + rr;
        float vals[6];
        float m = -INFINITY;
        #pragma unroll
        for (int i = 0; i < 6; i++){
            int col = lane + 32*i;
            bool ok = (col >= row) && (col < row + WINDOW) && (q0 + col < TT);
            float s = ok ? (Ss[row*200 + col] - (float)(col - row)*slope) : -INFINITY;
            vals[i] = s;
            m = fmaxf(m, s);
        }
        #pragma unroll
        for (int o = 16; o; o >>= 1) m = fmaxf(m, __shfl_xor_sync(0xffffffffu, m, o));
        float sum = 0.0f;
        #pragma unroll
        for (int i = 0; i < 6; i++){
            float p = (vals[i] > -INFINITY) ? __expf(vals[i] - m) : 0.0f;
            vals[i] = p; sum += p;
        }
        #pragma unroll
        for (int o = 16; o; o >>= 1) sum += __shfl_xor_sync(0xffffffffu, sum, o);
        float inv = 1.0f / sum;
        #pragma unroll
        for (int i = 0; i < 6; i++){
            int col = lane + 32*i;
            Ss[row*200 + col] = tf32r(vals[i]*inv);
        }
    }
    __syncthreads();

    {   // O[64,64] = P @ V
        wmma::fragment<wmma::accumulator,16,16,8,float> acc[2];
        wmma::fill_fragment(acc[0], 0.0f);
        wmma::fill_fragment(acc[1], 0.0f);
        #pragma unroll
        for (int j = 0; j < 192; j += 8){
            wmma::fragment<wmma::matrix_a,16,16,8,wmma::precision::tf32,wmma::row_major> af;
            wmma::load_matrix_sync(af, Ss + wr*16*200 + j, 200);
            #pragma unroll
            for (int f = 0; f < 2; f++){
                wmma::fragment<wmma::matrix_b,16,16,8,wmma::precision::tf32,wmma::row_major> bf;
                wmma::load_matrix_sync(bf, Vs + j*68 + wc*32 + f*16, 68);
                wmma::mma_sync(acc[f], af, bf, acc[f]);
            }
        }
        wmma::store_matrix_sync(Qs + wr*16*68 + wc*32,      acc[0], 68, wmma::mem_row_major);
        wmma::store_matrix_sync(Qs + wr*16*68 + wc*32 + 16, acc[1], 68, wmma::mem_row_major);
    }
    __syncthreads();

    #pragma unroll
    for (int it = 0; it < 4; it++){             // write split bf16 [B,T,D]
        int idx = tid + it*256;
        int row = idx >> 4, c4 = (idx & 15) << 2;
        float4 v = *(const float4*)(Qs + row*68 + c4);
        size_t o = (size_t)(b*TT + q0 + row)*DD + h*HD + c4;
        __nv_bfloat16 h0=__float2bfloat16(v.x), h1=__float2bfloat16(v.y),
                      h2=__float2bfloat16(v.z), h3=__float2bfloat16(v.w);
        *(__nv_bfloat162*)(g_ath+o)   = __nv_bfloat162(h0,h1);
        *(__nv_bfloat162*)(g_ath+o+2) = __nv_bfloat162(h2,h3);
        *(__nv_bfloat162*)(g_atl+o)   = __nv_bfloat162(__float2bfloat16(v.x-__bfloat162float(h0)),
                                                       __float2bfloat16(v.y-__bfloat162float(h1)));
        *(__nv_bfloat162*)(g_atl+o+2) = __nv_bfloat162(__float2bfloat16(v.z-__bfloat162float(h2)),
                                                       __float2bfloat16(v.w-__bfloat162float(h3)));
    }
}

// =====================================================================
extern "C" void kernel_launch(void* const* d_in, const int* in_sizes, int n_in,
                              void* d_out, int out_size)
{
    const float* x  = (const float*)d_in[0];
    const float* Wq = (const float*)d_in[1];
    const float* Wk = (const float*)d_in[2];
    const float* Wv = (const float*)d_in[3];
    const float* Wo = (const float*)d_in[4];
    float* out = (float*)d_out;

    cudaFuncSetAttribute(gemm_kernel, cudaFuncAttributeMaxDynamicSharedMemorySize,
                         GEMM_SMEM_BYTES);
    cudaFuncSetAttribute(attn_kernel, cudaFuncAttributeMaxDynamicSharedMemorySize,
                         ATTN_SMEM_BYTES);

    // 0) precision split of x and weights
    split_kernel<<<8192, 256>>>(x, Wq, Wk, Wv, Wo);
    // 1) fused QKV projection + per-head l2norm  [M=4096 x N=3072]
    gemm_kernel<<<dim3(24, 32), 512, GEMM_SMEM_BYTES>>>(nullptr, 0);
    // 2) sliding-window attention per (b, h, 64-query tile)
    attn_kernel<<<dim3(TT/64, HH, BB), 256, ATTN_SMEM_BYTES>>>();
    // 3) output projection  [M=4096 x N=1024]
    gemm_kernel<<<dim3(8, 32), 512, GEMM_SMEM_BYTES>>>(out, 1);
}

// round 5
// speedup vs baseline: 3.0983x; 1.0576x over previous
#include <cuda_runtime.h>
#include <cuda_bf16.h>
#include <mma.h>
#include <math.h>
#include <cstdint>

using namespace nvcuda;

#define BB 2
#define TT 2048
#define DD 1024
#define HH 16
#define HD 64
#define NROWS (BB*TT)      // 4096
#define WINDOW 128
#define MM (1024*1024)

// ---------------- scratch (device globals: allocation-free) ----------------
__device__ float g_q[(size_t)BB*HH*TT*HD];
__device__ float g_k[(size_t)BB*HH*TT*HD];
__device__ float g_v[(size_t)BB*HH*TT*HD];
__device__ __nv_bfloat16 g_xh[(size_t)NROWS*DD];
__device__ __nv_bfloat16 g_xl[(size_t)NROWS*DD];
__device__ __nv_bfloat16 g_wh[(size_t)4*MM];
__device__ __nv_bfloat16 g_wl[(size_t)4*MM];
__device__ __nv_bfloat16 g_ath[(size_t)NROWS*DD];
__device__ __nv_bfloat16 g_atl[(size_t)NROWS*DD];

__device__ __forceinline__ float tf32r(float x){
    unsigned u;
    asm("cvt.rna.tf32.f32 %0, %1;" : "=r"(u) : "f"(x));
    return __uint_as_float(u);
}
__device__ __forceinline__ uint32_t smem_u32(const void* p){
    uint32_t a;
    asm("{ .reg .u64 t; cvta.to.shared.u64 t, %1; cvt.u32.u64 %0, t; }" : "=r"(a) : "l"(p));
    return a;
}
__device__ __forceinline__ void cp16(uint32_t s, const void* g){
    asm volatile("cp.async.cg.shared.global [%0], [%1], 16;" :: "r"(s), "l"(g));
}

// =====================================================================
// split prep: fp32 -> bf16 hi/lo for x and all four weight matrices.
// =====================================================================
__global__ void __launch_bounds__(256) split_kernel(
    const float* __restrict__ x,
    const float* __restrict__ wq, const float* __restrict__ wk,
    const float* __restrict__ wv, const float* __restrict__ wo)
{
    size_t fi = (size_t)blockIdx.x*256 + threadIdx.x;
    const float* src; __nv_bfloat16 *dh, *dl; size_t base;
    if (fi < 1048576){ src = x; dh = g_xh; dl = g_xl; base = fi; }
    else {
        size_t r = fi - 1048576;
        int m = (int)(r >> 18);
        base = r & 262143;
        src = (m==0)?wq:(m==1)?wk:(m==2)?wv:wo;
        dh = g_wh + (size_t)m*MM; dl = g_wl + (size_t)m*MM;
    }
    float4 v = ((const float4*)src)[base];
    size_t e = base*4;
    __nv_bfloat16 h0=__float2bfloat16(v.x), h1=__float2bfloat16(v.y),
                  h2=__float2bfloat16(v.z), h3=__float2bfloat16(v.w);
    *(__nv_bfloat162*)(dh+e)   = __nv_bfloat162(h0,h1);
    *(__nv_bfloat162*)(dh+e+2) = __nv_bfloat162(h2,h3);
    *(__nv_bfloat162*)(dl+e)   = __nv_bfloat162(__float2bfloat16(v.x-__bfloat162float(h0)),
                                                __float2bfloat16(v.y-__bfloat162float(h1)));
    *(__nv_bfloat162*)(dl+e+2) = __nv_bfloat162(__float2bfloat16(v.z-__bfloat162float(h2)),
                                                __float2bfloat16(v.w-__bfloat162float(h3)));
}

// =====================================================================
// GEMM (3xBF16 split, fp32 acc), legacy wmma path, heavy warp tiles.
// CTA: M=256 x N=128, 256 threads / 8 warps (4 M-warps x 2 N-warps).
// Warp tile: 64x64 -> 4x4 accum frags; 48 MMAs per 16 frag loads.
// 3-stage cp.async pipeline, BK=32, ONE __syncthreads per chunk.
// smem/stage: Ah[256][40] Al Bh[128][40] Bl bf16 = 61440 B; x3 = 184320 B.
//   mode 0: A = x(split), B = Wq|Wk|Wv block; per-head l2norm epilogue.
//   mode 1: A = att(split), B = Wo; fp32 out.
// =====================================================================
#define NCH 32
#define SSTRIDE 40
#define STAGE_EL 30720                  // bf16 elems per stage
#define STAGE_BY 61440
#define GEMM_SMEM (3*STAGE_BY)          // 184320

__global__ void __launch_bounds__(256) gemm_kernel(float* __restrict__ out, int mode)
{
    extern __shared__ __nv_bfloat16 sb[];
    float* Cs = (float*)sb;                       // [256][132] after mainloop

    const int tid = threadIdx.x, w = tid >> 5, lane = tid & 31;
    const int r0 = blockIdx.y * 256;
    const int nb = blockIdx.x * 128;

    int which, col0;
    const __nv_bfloat16 *A_h, *A_l;
    if (mode == 0){ which = nb >> 10; col0 = nb & 1023; A_h = g_xh; A_l = g_xl; }
    else          { which = 3;        col0 = nb;        A_h = g_ath; A_l = g_atl; }
    const __nv_bfloat16* W_h = g_wh + (size_t)which*MM;
    const __nv_bfloat16* W_l = g_wl + (size_t)which*MM;

    const uint32_t ab = smem_u32(sb);

    auto loadc = [&](int c){
        uint32_t st = ab + (uint32_t)(c % 3) * STAGE_BY;
        int ko = c * 32;
        #pragma unroll
        for (int i = 0; i < 4; i++){               // A: 256 rows x 4 segs of 8 bf16
            int idx = tid + i*256;
            int row = idx >> 2, seg = idx & 3;
            uint32_t so = (uint32_t)(row*80 + seg*16);
            size_t go = (size_t)(r0 + row)*DD + ko + seg*8;
            cp16(st + so,          A_h + go);
            cp16(st + 20480u + so, A_l + go);
        }
        #pragma unroll
        for (int i = 0; i < 2; i++){               // B: 128 rows x 4 segs
            int idx = tid + i*256;
            int row = idx >> 2, seg = idx & 3;
            uint32_t so = (uint32_t)(row*80 + seg*16);
            size_t go = (size_t)(col0 + row)*DD + ko + seg*8;
            cp16(st + 40960u + so, W_h + go);
            cp16(st + 51200u + so, W_l + go);
        }
        asm volatile("cp.async.commit_group;");
    };

    wmma::fragment<wmma::accumulator,16,16,16,float> acc[4][4];
    #pragma unroll
    for (int i = 0; i < 4; i++)
        #pragma unroll
        for (int j = 0; j < 4; j++) wmma::fill_fragment(acc[i][j], 0.0f);

    const int wm = (w >> 1) * 64;      // warp M offset: 0/64/128/192
    const int wn = (w & 1) * 64;       // warp N offset: 0/64

    loadc(0); loadc(1);
    for (int c = 0; c < NCH; c++){
        if (c < NCH-1) asm volatile("cp.async.wait_group 1;");
        else           asm volatile("cp.async.wait_group 0;");
        __syncthreads();
        if (c + 2 < NCH) loadc(c + 2);

        const __nv_bfloat16* s = sb + (c % 3) * STAGE_EL;
        const __nv_bfloat16* sAh = s;
        const __nv_bfloat16* sAl = s + 10240;
        const __nv_bfloat16* sBh = s + 20480;
        const __nv_bfloat16* sBl = s + 25600;

        #pragma unroll
        for (int kk = 0; kk < 32; kk += 16){
            wmma::fragment<wmma::matrix_a,16,16,16,__nv_bfloat16,wmma::row_major> ah[4], al[4];
            #pragma unroll
            for (int i = 0; i < 4; i++){
                wmma::load_matrix_sync(ah[i], sAh + (wm + i*16)*SSTRIDE + kk, SSTRIDE);
                wmma::load_matrix_sync(al[i], sAl + (wm + i*16)*SSTRIDE + kk, SSTRIDE);
            }
            #pragma unroll
            for (int j = 0; j < 4; j++){
                wmma::fragment<wmma::matrix_b,16,16,16,__nv_bfloat16,wmma::col_major> bh, bl;
                wmma::load_matrix_sync(bh, sBh + (wn + j*16)*SSTRIDE + kk, SSTRIDE);
                wmma::load_matrix_sync(bl, sBl + (wn + j*16)*SSTRIDE + kk, SSTRIDE);
                #pragma unroll
                for (int i = 0; i < 4; i++){
                    wmma::mma_sync(acc[i][j], ah[i], bh, acc[i][j]);   // hi*hi
                    wmma::mma_sync(acc[i][j], ah[i], bl, acc[i][j]);   // hi*lo
                    wmma::mma_sync(acc[i][j], al[i], bh, acc[i][j]);   // lo*hi
                }
            }
        }
    }
    __syncthreads();

    // stage C in smem [256][132]
    #pragma unroll
    for (int i = 0; i < 4; i++)
        #pragma unroll
        for (int j = 0; j < 4; j++)
            wmma::store_matrix_sync(Cs + (wm + i*16)*132 + wn + j*16,
                                    acc[i][j], 132, wmma::mem_row_major);
    __syncthreads();

    // epilogue: warp w -> rows [w*32, w*32+32); lane covers 4 cols
    #pragma unroll
    for (int rr = 0; rr < 32; rr++){
        int row = w*32 + rr;
        int gt = r0 + row;
        float v0 = Cs[row*132 + lane];
        float v1 = Cs[row*132 + lane + 32];
        float v2 = Cs[row*132 + lane + 64];
        float v3 = Cs[row*132 + lane + 96];
        if (mode == 0){
            float s0 = 1.0f, s1 = 1.0f;
            if (which < 2){
                float ssa = v0*v0 + v1*v1;
                float ssb = v2*v2 + v3*v3;
                #pragma unroll
                for (int o = 16; o; o >>= 1){
                    ssa += __shfl_xor_sync(0xffffffffu, ssa, o);
                    ssb += __shfl_xor_sync(0xffffffffu, ssb, o);
                }
                s0 = 1.0f / fmaxf(sqrtf(ssa), 1e-6f);
                s1 = 1.0f / fmaxf(sqrtf(ssb), 1e-6f);
            }
            int bq = gt >> 11, t = gt & (TT-1);
            float* arr = (which==0) ? g_q : ((which==1) ? g_k : g_v);
            int hh0 = col0 >> 6;
            float* d0 = arr + ((size_t)(bq*HH + hh0  )*TT + t)*HD;
            float* d1 = arr + ((size_t)(bq*HH + hh0+1)*TT + t)*HD;
            d0[lane]      = v0*s0;
            d0[lane + 32] = v1*s0;
            d1[lane]      = v2*s1;
            d1[lane + 32] = v3*s1;
        } else {
            float* d = out + (size_t)gt*DD + nb;
            d[lane]      = v0;
            d[lane + 32] = v1;
            d[lane + 64] = v2;
            d[lane + 96] = v3;
        }
    }
}

// =====================================================================
// Attention kernel (tf32 wmma): one block per (b,h,64-q tile).
// Output written as bf16 hi/lo split (feeds Wo GEMM).
// =====================================================================
#define ATTN_SMEM_FLOATS (64*68 + 192*68 + 192*68 + 64*200)
#define ATTN_SMEM_BYTES  (ATTN_SMEM_FLOATS*4)

__global__ void __launch_bounds__(256) attn_kernel()
{
    extern __shared__ float sm[];
    float* Qs = sm;                  // [64][68]
    float* Ks = sm + 64*68;          // [192][68]
    float* Vs = Ks + 192*68;         // [192][68]
    float* Ss = Vs + 192*68;         // [64][200]

    const int tid = threadIdx.x, w = tid >> 5, lane = tid & 31;
    const int q0 = blockIdx.x * 64;
    const int h  = blockIdx.y, b = blockIdx.z;
    const size_t base = ((size_t)(b*HH + h)*TT)*HD;
    const float* qb = g_q + base;
    const float* kb = g_k + base;
    const float* vb = g_v + base;

    #pragma unroll
    for (int it = 0; it < 4; it++){
        int idx = tid + it*256;
        int row = idx >> 4, c4 = (idx & 15) << 2;
        float4 v = *(const float4*)(qb + (size_t)(q0 + row)*HD + c4);
        int o = row*68 + c4;
        Qs[o]=tf32r(v.x); Qs[o+1]=tf32r(v.y); Qs[o+2]=tf32r(v.z); Qs[o+3]=tf32r(v.w);
    }
    #pragma unroll
    for (int it = 0; it < 12; it++){
        int idx = tid + it*256;
        int row = idx >> 4, c4 = (idx & 15) << 2;
        int jg = q0 + row;
        float4 kv = make_float4(0.f,0.f,0.f,0.f), vv = kv;
        if (jg < TT){
            kv = *(const float4*)(kb + (size_t)jg*HD + c4);
            vv = *(const float4*)(vb + (size_t)jg*HD + c4);
        }
        int o = row*68 + c4;
        Ks[o]=tf32r(kv.x); Ks[o+1]=tf32r(kv.y); Ks[o+2]=tf32r(kv.z); Ks[o+3]=tf32r(kv.w);
        Vs[o]=tf32r(vv.x); Vs[o+1]=tf32r(vv.y); Vs[o+2]=tf32r(vv.z); Vs[o+3]=tf32r(vv.w);
    }
    __syncthreads();

    const int wr = w & 3, wc = w >> 2;

    {   // S[64,192] = Q @ K^T
        wmma::fragment<wmma::accumulator,16,16,8,float> acc[6];
        #pragma unroll
        for (int f = 0; f < 6; f++) wmma::fill_fragment(acc[f], 0.0f);
        #pragma unroll
        for (int d = 0; d < HD; d += 8){
            wmma::fragment<wmma::matrix_a,16,16,8,wmma::precision::tf32,wmma::row_major> af;
            wmma::load_matrix_sync(af, Qs + wr*16*68 + d, 68);
            #pragma unroll
            for (int f = 0; f < 6; f++){
                wmma::fragment<wmma::matrix_b,16,16,8,wmma::precision::tf32,wmma::col_major> bf;
                wmma::load_matrix_sync(bf, Ks + (wc*96 + f*16)*68 + d, 68);
                wmma::mma_sync(acc[f], af, bf, acc[f]);
            }
        }
        #pragma unroll
        for (int f = 0; f < 6; f++)
            wmma::store_matrix_sync(Ss + wr*16*200 + wc*96 + f*16, acc[f], 200,
                                    wmma::mem_row_major);
    }
    __syncthreads();

    const float slope = exp2f(-8.0f * (float)h / 15.0f);
    #pragma unroll
    for (int rr = 0; rr < 8; rr++){
        int row = w*8 + rr;
        float vals[6];
        float m = -INFINITY;
        #pragma unroll
        for (int i = 0; i < 6; i++){
            int col = lane + 32*i;
            bool ok = (col >= row) && (col < row + WINDOW) && (q0 + col < TT);
            float s = ok ? (Ss[row*200 + col] - (float)(col - row)*slope) : -INFINITY;
            vals[i] = s;
            m = fmaxf(m, s);
        }
        #pragma unroll
        for (int o = 16; o; o >>= 1) m = fmaxf(m, __shfl_xor_sync(0xffffffffu, m, o));
        float sum = 0.0f;
        #pragma unroll
        for (int i = 0; i < 6; i++){
            float p = (vals[i] > -INFINITY) ? __expf(vals[i] - m) : 0.0f;
            vals[i] = p; sum += p;
        }
        #pragma unroll
        for (int o = 16; o; o >>= 1) sum += __shfl_xor_sync(0xffffffffu, sum, o);
        float inv = 1.0f / sum;
        #pragma unroll
        for (int i = 0; i < 6; i++){
            int col = lane + 32*i;
            Ss[row*200 + col] = tf32r(vals[i]*inv);
        }
    }
    __syncthreads();

    {   // O[64,64] = P @ V
        wmma::fragment<wmma::accumulator,16,16,8,float> acc[2];
        wmma::fill_fragment(acc[0], 0.0f);
        wmma::fill_fragment(acc[1], 0.0f);
        #pragma unroll
        for (int j = 0; j < 192; j += 8){
            wmma::fragment<wmma::matrix_a,16,16,8,wmma::precision::tf32,wmma::row_major> af;
            wmma::load_matrix_sync(af, Ss + wr*16*200 + j, 200);
            #pragma unroll
            for (int f = 0; f < 2; f++){
                wmma::fragment<wmma::matrix_b,16,16,8,wmma::precision::tf32,wmma::row_major> bf;
                wmma::load_matrix_sync(bf, Vs + j*68 + wc*32 + f*16, 68);
                wmma::mma_sync(acc[f], af, bf, acc[f]);
            }
        }
        wmma::store_matrix_sync(Qs + wr*16*68 + wc*32,      acc[0], 68, wmma::mem_row_major);
        wmma::store_matrix_sync(Qs + wr*16*68 + wc*32 + 16, acc[1], 68, wmma::mem_row_major);
    }
    __syncthreads();

    #pragma unroll
    for (int it = 0; it < 4; it++){             // write split bf16 [B,T,D]
        int idx = tid + it*256;
        int row = idx >> 4, c4 = (idx & 15) << 2;
        float4 v = *(const float4*)(Qs + row*68 + c4);
        size_t o = (size_t)(b*TT + q0 + row)*DD + h*HD + c4;
        __nv_bfloat16 h0=__float2bfloat16(v.x), h1=__float2bfloat16(v.y),
                      h2=__float2bfloat16(v.z), h3=__float2bfloat16(v.w);
        *(__nv_bfloat162*)(g_ath+o)   = __nv_bfloat162(h0,h1);
        *(__nv_bfloat162*)(g_ath+o+2) = __nv_bfloat162(h2,h3);
        *(__nv_bfloat162*)(g_atl+o)   = __nv_bfloat162(__float2bfloat16(v.x-__bfloat162float(h0)),
                                                       __float2bfloat16(v.y-__bfloat162float(h1)));
        *(__nv_bfloat162*)(g_atl+o+2) = __nv_bfloat162(__float2bfloat16(v.z-__bfloat162float(h2)),
                                                       __float2bfloat16(v.w-__bfloat162float(h3)));
    }
}

// =====================================================================
extern "C" void kernel_launch(void* const* d_in, const int* in_sizes, int n_in,
                              void* d_out, int out_size)
{
    const float* x  = (const float*)d_in[0];
    const float* Wq = (const float*)d_in[1];
    const float* Wk = (const float*)d_in[2];
    const float* Wv = (const float*)d_in[3];
    const float* Wo = (const float*)d_in[4];
    float* out = (float*)d_out;

    cudaFuncSetAttribute(gemm_kernel, cudaFuncAttributeMaxDynamicSharedMemorySize,
                         GEMM_SMEM);
    cudaFuncSetAttribute(attn_kernel, cudaFuncAttributeMaxDynamicSharedMemorySize,
                         ATTN_SMEM_BYTES);

    // 0) precision split of x and weights
    split_kernel<<<8192, 256>>>(x, Wq, Wk, Wv, Wo);
    // 1) fused QKV projection + per-head l2norm  [M=4096 x N=3072]
    gemm_kernel<<<dim3(24, 16), 256, GEMM_SMEM>>>(nullptr, 0);
    // 2) sliding-window attention per (b, h, 64-query tile)
    attn_kernel<<<dim3(TT/64, HH, BB), 256, ATTN_SMEM_BYTES>>>();
    // 3) output projection  [M=4096 x N=1024]
    gemm_kernel<<<dim3(8, 16), 256, GEMM_SMEM>>>(out, 1);
}